// round 14
// baseline (speedup 1.0000x reference)
#include <cuda_runtime.h>
#include <cuda_bf16.h>
#include <cstdint>

// Embedding gather: out[t, :] = weight[token_ids[t], :]
// d_in[0] = token_ids (int32) [8192], d_in[1] = weight fp32 [32000,1024]
// d_out = fp32 [8192,1024]
//
// Persistent single-wave kernel: 1184 CTAs (8 per SM on 148 SMs), 256 threads.
// Grid-stride over tokens with a depth-1 software pipeline: the NEXT token's
// index load and row load are issued (ordered volatile asm) BEFORE the
// current row's store, so each warp keeps a continuous, never-draining load
// stream with zero CTA churn and zero wave transitions.

static constexpr int D4      = 256;   // float4s per row (1024 floats)
static constexpr int THREADS = 256;
static constexpr int CTAS    = 1184;  // 148 SMs * 8 resident CTAs

__global__ __launch_bounds__(THREADS)
void embedding_gather_persistent_kernel(const int* __restrict__ token_ids,
                                        const float4* __restrict__ weight,
                                        float4* __restrict__ out,
                                        int n_tokens) {
    const int tid    = threadIdx.x;
    const int stride = gridDim.x;

    int t = blockIdx.x;
    if (t >= n_tokens) return;

    // Prologue: first token's row in flight.
    int row = __ldg(token_ids + t);
    float a, b, c, d;
    {
        const float4* s = weight + (size_t)row * D4 + tid;
        asm volatile("ld.global.nc.v4.f32 {%0,%1,%2,%3}, [%4];"
                     : "=f"(a), "=f"(b), "=f"(c), "=f"(d) : "l"(s));
    }

    // Steady state: issue next loads before current store (order pinned by
    // volatile asm), so the load pipe never drains behind a store.
    for (int t2 = t + stride; t2 < n_tokens; t2 += stride) {
        const int row2 = __ldg(token_ids + t2);
        const float4* s2 = weight + (size_t)row2 * D4 + tid;

        float a2, b2, c2, d2;
        asm volatile("ld.global.nc.v4.f32 {%0,%1,%2,%3}, [%4];"
                     : "=f"(a2), "=f"(b2), "=f"(c2), "=f"(d2) : "l"(s2));

        float4* dst = out + (size_t)t * D4 + tid;
        asm volatile("st.global.v4.f32 [%0], {%1,%2,%3,%4};"
                     :: "l"(dst), "f"(a), "f"(b), "f"(c), "f"(d) : "memory");

        a = a2; b = b2; c = c2; d = d2;
        t = t2;
    }

    // Epilogue: final store.
    float4* dst = out + (size_t)t * D4 + tid;
    asm volatile("st.global.v4.f32 [%0], {%1,%2,%3,%4};"
                 :: "l"(dst), "f"(a), "f"(b), "f"(c), "f"(d) : "memory");
}

extern "C" void kernel_launch(void* const* d_in, const int* in_sizes, int n_in,
                              void* d_out, int out_size) {
    const int* token_ids = (const int*)d_in[0];
    const float4* weight = (const float4*)d_in[1];
    float4* out          = (float4*)d_out;

    int n_tokens = in_sizes[0];   // 8192

    embedding_gather_persistent_kernel<<<CTAS, THREADS>>>(token_ids, weight, out,
                                                          n_tokens);
}

// round 15
// speedup vs baseline: 1.1995x; 1.1995x over previous
#include <cuda_runtime.h>
#include <cuda_bf16.h>
#include <cstdint>

// Embedding gather: out[t, :] = weight[token_ids[t], :]
// d_in[0] = token_ids (int32) [8192], d_in[1] = weight fp32 [32000,1024]
// d_out = fp32 [8192,1024]
//
// Champion structure (R1: one 4 KB row per 256-thread group, float4 loads
// via __ldg), packed 2 tokens per 512-thread CTA to halve CTA dispatch count
// (4096 CTAs). Per-thread work and memory pattern identical to R1.

static constexpr int D4      = 256;   // float4s per row (1024 floats)
static constexpr int THREADS = 512;   // 2 row-groups of 256 threads
static constexpr int TPC     = 2;     // tokens per CTA

__global__ __launch_bounds__(THREADS)
void embedding_gather_kernel(const int* __restrict__ token_ids,
                             const float4* __restrict__ weight,
                             float4* __restrict__ out) {
    const int local = threadIdx.x >> 8;          // which token in this CTA (0..1)
    const int chunk = threadIdx.x & 255;         // float4 index within the row
    const int t = blockIdx.x * TPC + local;

    const int row = __ldg(token_ids + t);

    const float4* src = weight + (size_t)row * D4 + chunk;
    float4*       dst = out    + (size_t)t   * D4 + chunk;

    *dst = __ldg(src);
}

extern "C" void kernel_launch(void* const* d_in, const int* in_sizes, int n_in,
                              void* d_out, int out_size) {
    const int* token_ids = (const int*)d_in[0];
    const float4* weight = (const float4*)d_in[1];
    float4* out          = (float4*)d_out;

    int n_tokens = in_sizes[0];          // 8192
    int n_ctas   = n_tokens / TPC;       // 4096

    embedding_gather_kernel<<<n_ctas, THREADS>>>(token_ids, weight, out);
}

// round 16
// speedup vs baseline: 1.3538x; 1.1287x over previous
#include <cuda_runtime.h>
#include <cuda_bf16.h>
#include <cstdint>

// Embedding gather: out[t, :] = weight[token_ids[t], :]
// d_in[0] = token_ids (int32) [8192], d_in[1] = weight fp32 [32000,1024]
// d_out = fp32 [8192,1024]
//
// Warp-per-token: each warp moves one 4 KB row. Each thread front-batches
// 8 consecutive float4 loads (lane-contiguous, 512 B per warp instruction,
// zero divergence) before any store -> per-thread MLP = 8 on the gather.
// 256 threads = 8 warps = 8 tokens per CTA; 1024 CTAs.

static constexpr int D4      = 256;  // float4s per row
static constexpr int THREADS = 256;
static constexpr int WPC     = 8;    // warps (tokens) per CTA
static constexpr int PER_THR = 8;    // float4s per thread (32 * 8 = 256)

__global__ __launch_bounds__(THREADS)
void embedding_gather_warp_kernel(const int* __restrict__ token_ids,
                                  const float4* __restrict__ weight,
                                  float4* __restrict__ out) {
    const int warp = threadIdx.x >> 5;
    const int lane = threadIdx.x & 31;
    const int t = blockIdx.x * WPC + warp;

    const int row = __ldg(token_ids + t);

    // Thread covers 8 float4s at stride 32 (each warp instr = 512 B contiguous).
    const float4* src = weight + (size_t)row * D4 + lane;
    float4*       dst = out    + (size_t)t   * D4 + lane;

    float v[PER_THR][4];
#pragma unroll
    for (int i = 0; i < PER_THR; ++i) {
        asm volatile("ld.global.nc.v4.f32 {%0,%1,%2,%3}, [%4];"
                     : "=f"(v[i][0]), "=f"(v[i][1]), "=f"(v[i][2]), "=f"(v[i][3])
                     : "l"(src + i * 32));
    }
#pragma unroll
    for (int i = 0; i < PER_THR; ++i) {
        asm volatile("st.global.v4.f32 [%0], {%1,%2,%3,%4};"
                     :: "l"(dst + i * 32),
                        "f"(v[i][0]), "f"(v[i][1]), "f"(v[i][2]), "f"(v[i][3])
                     : "memory");
    }
}

extern "C" void kernel_launch(void* const* d_in, const int* in_sizes, int n_in,
                              void* d_out, int out_size) {
    const int* token_ids = (const int*)d_in[0];
    const float4* weight = (const float4*)d_in[1];
    float4* out          = (float4*)d_out;

    int n_tokens = in_sizes[0];        // 8192
    int n_ctas   = n_tokens / WPC;     // 1024

    embedding_gather_warp_kernel<<<n_ctas, THREADS>>>(token_ids, weight, out);
}